// round 13
// baseline (speedup 1.0000x reference)
#include <cuda_runtime.h>
#include <math.h>
#include <stdint.h>

// ---------------- scratch activations (alloc-free: __device__ globals) ----------------
__device__ float g_act1[8 * 32 * 256 * 256];   // 64 MB
__device__ float g_act2[8 * 64 * 128 * 128];   // 32 MB
__device__ float g_act3[8 * 128 * 64 * 64];    // 16 MB
__device__ float g_act4[8 * 256 * 32 * 32];    //  8 MB

// Kahan compensated add: s += v with compensation c. Pure add/sub (safe from fmad).
__device__ __forceinline__ void kadd(float& s, float& c, float v) {
    float y = v - c;
    float t = s + y;
    c = (t - s) - y;
    s = t;
}

// ---------------- fused conv3x3(SAME) + bias + relu + maxpool2x2 ----------------
// Each thread: one pooled output pixel (2x2 pre-pool quad) for CB output channels.
// Accumulation: 9-tap FMA partial per input channel, Kahan-compensated across channels
// -> accumulator error ~2e-7 relative instead of sqrt(n)-ulp random walk.
template<int CIN, int COUT, int HIN, int WIN, int CB>
__global__ void __launch_bounds__(256) conv_pool_kernel(
    const float* __restrict__ in, const float* __restrict__ w,
    const float* __restrict__ bias, float* __restrict__ out)
{
    constexpr int TW = 16, TH = 16;
    constexpr int HOUT = HIN / 2, WOUT = WIN / 2;
    constexpr int TIW = 2 * TW + 2;   // 34
    constexpr int TIH = 2 * TH + 2;   // 34

    __shared__ float wsm[CB * CIN * 9];
    __shared__ float bsm[CB];
    __shared__ float tile[TIH][TIW];

    const int tid = threadIdx.x;
    const int tx = tid % TW;
    const int ty = tid / TW;

    constexpr int GROUPS = COUT / CB;
    const int b  = blockIdx.z / GROUPS;
    const int c0 = (blockIdx.z % GROUPS) * CB;

    for (int i = tid; i < CB * CIN * 9; i += 256)
        wsm[i] = w[(size_t)c0 * CIN * 9 + i];
    if (tid < CB) bsm[tid] = bias[c0 + tid];

    const int px0 = blockIdx.x * TW;
    const int py0 = blockIdx.y * TH;
    const int gx0 = px0 * 2 - 1;   // input col of tile col 0 (SAME halo)
    const int gy0 = py0 * 2 - 1;

    float acc[CB][4], cmp[CB][4];
#pragma unroll
    for (int cb = 0; cb < CB; cb++)
#pragma unroll
        for (int q = 0; q < 4; q++) { acc[cb][q] = 0.0f; cmp[cb][q] = 0.0f; }

    const float* inb = in + (size_t)b * CIN * HIN * WIN;

    for (int cin = 0; cin < CIN; cin++) {
        __syncthreads();
        const float* ip = inb + (size_t)cin * HIN * WIN;
        for (int i = tid; i < TIH * TIW; i += 256) {
            int r = i / TIW, c = i % TIW;
            int gy = gy0 + r, gx = gx0 + c;
            float v = 0.0f;
            if (gy >= 0 && gy < HIN && gx >= 0 && gx < WIN)
                v = ip[(size_t)gy * WIN + gx];
            tile[r][c] = v;
        }
        __syncthreads();

        float p[4][4];
#pragma unroll
        for (int r = 0; r < 4; r++)
#pragma unroll
            for (int c = 0; c < 4; c++)
                p[r][c] = tile[2 * ty + r][2 * tx + c];

        const float* wc = wsm + cin * 9;
#pragma unroll
        for (int cb = 0; cb < CB; cb++) {
            const float* wk = wc + cb * CIN * 9;
            float part[4] = {0.0f, 0.0f, 0.0f, 0.0f};
#pragma unroll
            for (int r = 0; r < 3; r++)
#pragma unroll
                for (int c = 0; c < 3; c++) {
                    float wv = wk[r * 3 + c];
                    part[0] = fmaf(wv, p[r][c],         part[0]);
                    part[1] = fmaf(wv, p[r][c + 1],     part[1]);
                    part[2] = fmaf(wv, p[r + 1][c],     part[2]);
                    part[3] = fmaf(wv, p[r + 1][c + 1], part[3]);
                }
#pragma unroll
            for (int q = 0; q < 4; q++)
                kadd(acc[cb][q], cmp[cb][q], part[q]);
        }
    }

    const int px = px0 + tx, py = py0 + ty;
#pragma unroll
    for (int cb = 0; cb < CB; cb++) {
        float m = fmaxf(fmaxf(acc[cb][0], acc[cb][1]),
                        fmaxf(acc[cb][2], acc[cb][3]));
        float v = fmaxf(m + bsm[cb], 0.0f);   // relu(max+bias) == max(relu(x+bias)), monotone
        out[(((size_t)b * COUT + c0 + cb) * HOUT + py) * WOUT + px] = v;
    }
}

// ---------------- head (1x1 conv) + decode + top-200 + greedy NMS, one block per batch ---------
__global__ void __launch_bounds__(1024) head_decode_kernel(
    const float* __restrict__ act4, const float* __restrict__ wh,
    const float* __restrict__ bh, float* __restrict__ out, int out_size)
{
    constexpr int NC = 1024, K = 200;
    const int b = blockIdx.x;
    const int tid = threadIdx.x;

    __shared__ float s_wh[5 * 256];
    __shared__ float s_x1[NC], s_y1[NC], s_x2[NC], s_y2[NC];
    __shared__ float s_sc[NC];
    __shared__ int   s_ix[NC];
    __shared__ float k_x1[K], k_y1[K], k_x2[K], k_y2[K], k_sv[K], k_ar[K];
    __shared__ int   k_keep[K];

    for (int i = tid; i < 5 * 256; i += 1024) s_wh[i] = wh[i];
    __syncthreads();

    // 1x1 head conv: Kahan over 256 channels
    float p0 = 0.f, p1 = 0.f, p2 = 0.f, p3 = 0.f, p4 = 0.f;
    float c0k = 0.f, c1k = 0.f, c2k = 0.f, c3k = 0.f, c4k = 0.f;
    const float* ab = act4 + (size_t)b * 256 * NC + tid;
#pragma unroll 4
    for (int c = 0; c < 256; c++) {
        float v = ab[(size_t)c * NC];
        kadd(p0, c0k, s_wh[0 * 256 + c] * v);
        kadd(p1, c1k, s_wh[1 * 256 + c] * v);
        kadd(p2, c2k, s_wh[2 * 256 + c] * v);
        kadd(p3, c3k, s_wh[3 * 256 + c] * v);
        kadd(p4, c4k, s_wh[4 * 256 + c] * v);
    }
    p0 += bh[0]; p1 += bh[1]; p2 += bh[2]; p3 += bh[3]; p4 += bh[4];

    // decode (transcendentals in double for correct rounding)
    const int gy = tid >> 5, gx = tid & 31;
    const float S = 16.0f;  // 512/32
    float obj = (float)(1.0 / (1.0 + exp(-(double)p0)));
    float sx  = (float)(1.0 / (1.0 + exp(-(double)p1)));
    float sy  = (float)(1.0 / (1.0 + exp(-(double)p2)));
    float bw  = (float)exp((double)p3) * S;
    float bhh = (float)exp((double)p4) * S;
    float cx = (float)gx * S + sx * S;
    float cy = (float)gy * S + sy * S;
    float x1 = fminf(fmaxf(cx - bw * 0.5f, 0.0f), 511.0f);
    float y1 = fminf(fmaxf(cy - bhh * 0.5f, 0.0f), 511.0f);
    float x2 = fminf(fmaxf(cx + bw * 0.5f, 0.0f), 511.0f);
    float y2 = fminf(fmaxf(cy + bhh * 0.5f, 0.0f), 511.0f);

    s_x1[tid] = x1; s_y1[tid] = y1; s_x2[tid] = x2; s_y2[tid] = y2;
    s_sc[tid] = (obj >= 0.01f) ? obj : -1.0f;
    s_ix[tid] = tid;
    __syncthreads();

    // bitonic sort: descending by score, ascending index on ties (stable like lax.top_k)
    for (int k = 2; k <= NC; k <<= 1) {
        for (int j = k >> 1; j > 0; j >>= 1) {
            int i = tid, ixj = i ^ j;
            if (ixj > i) {
                float sa = s_sc[i], sb = s_sc[ixj];
                int   ia = s_ix[i], ib = s_ix[ixj];
                bool iBetter = (sa > sb) || (sa == sb && ia < ib);
                bool desc = ((i & k) == 0);
                if (desc ? !iBetter : iBetter) {
                    s_sc[i] = sb; s_sc[ixj] = sa;
                    s_ix[i] = ib; s_ix[ixj] = ia;
                }
            }
            __syncthreads();
        }
    }

    // gather top-200
    if (tid < K) {
        int id = s_ix[tid];
        float sv = s_sc[tid];
        float bx1 = s_x1[id], by1 = s_y1[id], bx2 = s_x2[id], by2 = s_y2[id];
        k_x1[tid] = bx1; k_y1[tid] = by1; k_x2[tid] = bx2; k_y2[tid] = by2;
        k_sv[tid] = sv;
        k_ar[tid] = (bx2 - bx1) * (by2 - by1);
        k_keep[tid] = (sv >= 0.01f) ? 1 : 0;
    }
    __syncthreads();

    // greedy NMS, exactly the reference suppression rule (fp32, same formula order)
    for (int i = 0; i < K; i++) {
        if (tid < K && tid > i && k_keep[i]) {
            float xx1 = fmaxf(k_x1[i], k_x1[tid]);
            float yy1 = fmaxf(k_y1[i], k_y1[tid]);
            float xx2 = fminf(k_x2[i], k_x2[tid]);
            float yy2 = fminf(k_y2[i], k_y2[tid]);
            float inter = fmaxf(xx2 - xx1, 0.0f) * fmaxf(yy2 - yy1, 0.0f);
            float uni = k_ar[i] + k_ar[tid] - inter;
            float iou = inter / fmaxf(uni, 1e-6f);
            if (iou > 0.5f) k_keep[tid] = 0;
        }
        __syncthreads();
    }

    // write out5 [B,K,5] then keep [B,K] (as float), if present
    if (tid < K) {
        float kf = k_keep[tid] ? 1.0f : 0.0f;
        float sv = k_sv[tid];
        float svv = (sv >= 0.01f) ? sv : 0.0f;
        float* o = out + ((size_t)b * K + tid) * 5;
        o[0] = k_x1[tid] * kf;
        o[1] = k_y1[tid] * kf;
        o[2] = k_x2[tid] * kf;
        o[3] = k_y2[tid] * kf;
        o[4] = svv * kf;
        if (out_size >= 8 * K * 5 + 8 * K)
            out[8 * K * 5 + (size_t)b * K + tid] = kf;
    }
}

// ---------------- launch ----------------
extern "C" void kernel_launch(void* const* d_in, const int* in_sizes, int n_in,
                              void* d_out, int out_size)
{
    const float* images = (const float*)d_in[0];
    const float* w1 = (const float*)d_in[1]; const float* b1 = (const float*)d_in[2];
    const float* w2 = (const float*)d_in[3]; const float* b2 = (const float*)d_in[4];
    const float* w3 = (const float*)d_in[5]; const float* b3 = (const float*)d_in[6];
    const float* w4 = (const float*)d_in[7]; const float* b4 = (const float*)d_in[8];
    const float* wh = (const float*)d_in[9]; const float* bh = (const float*)d_in[10];

    float *a1, *a2, *a3, *a4;
    cudaGetSymbolAddress((void**)&a1, g_act1);
    cudaGetSymbolAddress((void**)&a2, g_act2);
    cudaGetSymbolAddress((void**)&a3, g_act3);
    cudaGetSymbolAddress((void**)&a4, g_act4);

    conv_pool_kernel<3, 32, 512, 512, 8><<<dim3(16, 16, 8 * (32 / 8)), 256>>>(images, w1, b1, a1);
    conv_pool_kernel<32, 64, 256, 256, 8><<<dim3(8, 8, 8 * (64 / 8)), 256>>>(a1, w2, b2, a2);
    conv_pool_kernel<64, 128, 128, 128, 8><<<dim3(4, 4, 8 * (128 / 8)), 256>>>(a2, w3, b3, a3);
    conv_pool_kernel<128, 256, 64, 64, 8><<<dim3(2, 2, 8 * (256 / 8)), 256>>>(a3, w4, b4, a4);
    head_decode_kernel<<<8, 1024>>>(a4, wh, bh, (float*)d_out, out_size);
}